// round 1
// baseline (speedup 1.0000x reference)
#include <cuda_runtime.h>
#include <math.h>

#define D_MODEL 1024
#define D_FF    4096
#define N_EXP   8
#define MAX_N   4096
#define MAX_PAIRS (2*MAX_N)

// ---- scratch (static device globals; no runtime allocation) ----
__device__ float g_H[(size_t)MAX_PAIRS * D_FF];        // GELU(x@W1) per pair
__device__ float g_pairout[(size_t)MAX_PAIRS * D_MODEL]; // per-pair FFN output (weighted)
__device__ int   g_pairlist[MAX_PAIRS];                // pair ids sorted by expert (stable)
__device__ int   g_cnt[N_EXP];
__device__ int   g_off[N_EXP];
__device__ int   g_tokexp[MAX_PAIRS];                  // expert id per pair (pair = 2*t+slot)
__device__ float g_tokw[MAX_PAIRS];                    // gate weight per pair

__device__ __forceinline__ float gelu_exact(float v) {
    return 0.5f * v * (1.0f + erff(v * 0.70710678118654752440f));
}

// ---------------- gate: logits -> softmax -> top2 ----------------
__global__ void gate_kernel(const float* __restrict__ x,
                            const float* __restrict__ gw, int N) {
    __shared__ float s_gw[N_EXP][D_MODEL];
    int tid = threadIdx.x;
    for (int i = tid; i < N_EXP * D_MODEL; i += blockDim.x)
        s_gw[i >> 10][i & 1023] = gw[i];
    __syncthreads();

    int warp = tid >> 5, lane = tid & 31;
    int t = blockIdx.x * 8 + warp;
    if (t >= N) return;

    const float* xr = x + (size_t)t * D_MODEL;
    float acc[N_EXP];
#pragma unroll
    for (int e = 0; e < N_EXP; e++) acc[e] = 0.f;

    for (int d = lane; d < D_MODEL; d += 32) {
        float xv = xr[d];
#pragma unroll
        for (int e = 0; e < N_EXP; e++) acc[e] += xv * s_gw[e][d];
    }
#pragma unroll
    for (int e = 0; e < N_EXP; e++) {
#pragma unroll
        for (int o = 16; o > 0; o >>= 1)
            acc[e] += __shfl_xor_sync(0xffffffffu, acc[e], o);
    }

    if (lane == 0) {
        float mx = acc[0];
#pragma unroll
        for (int e = 1; e < N_EXP; e++) mx = fmaxf(mx, acc[e]);
        float p[N_EXP]; float sum = 0.f;
#pragma unroll
        for (int e = 0; e < N_EXP; e++) { p[e] = expf(acc[e] - mx); sum += p[e]; }
        float inv = 1.0f / sum;
#pragma unroll
        for (int e = 0; e < N_EXP; e++) p[e] *= inv;

        int e0 = 0;
#pragma unroll
        for (int e = 1; e < N_EXP; e++) if (p[e] > p[e0]) e0 = e;
        int e1 = (e0 == 0) ? 1 : 0;
#pragma unroll
        for (int e = 0; e < N_EXP; e++) if (e != e0 && p[e] > p[e1]) e1 = e;

        g_tokexp[2 * t + 0] = e0; g_tokw[2 * t + 0] = p[e0];
        g_tokexp[2 * t + 1] = e1; g_tokw[2 * t + 1] = p[e1];
    }
}

// ------- deterministic per-expert compaction (stable counting sort) -------
__global__ void build_kernel(int N) {
    __shared__ int s_cnt[N_EXP];
    int tid = threadIdx.x, warp = tid >> 5, lane = tid & 31;
    int total = 2 * N;

    // count pass: warp e counts entries with expert == e
    if (warp < N_EXP) {
        int c = 0;
        for (int i = lane; i < total; i += 32) c += (g_tokexp[i] == warp);
#pragma unroll
        for (int o = 16; o > 0; o >>= 1) c += __shfl_xor_sync(0xffffffffu, c, o);
        if (lane == 0) s_cnt[warp] = c;
    }
    __syncthreads();
    if (tid == 0) {
        int o = 0;
        for (int e = 0; e < N_EXP; e++) { g_off[e] = o; g_cnt[e] = s_cnt[e]; o += s_cnt[e]; }
    }
    __syncthreads();

    // place pass: stable order by pair id
    if (warp < N_EXP) {
        int run = g_off[warp];
        for (int base = 0; base < total; base += 32) {
            int i = base + lane;
            bool m = (i < total) && (g_tokexp[i] == warp);
            unsigned b = __ballot_sync(0xffffffffu, m);
            if (m) g_pairlist[run + __popc(b & ((1u << lane) - 1u))] = i;
            run += __popc(b);
        }
    }
}

// ---------------- GEMM1: H[p,f] = gelu( x[tok(p),:] @ W1[e] ) ----------------
#define BM 64
#define BN 64
#define BK 16

__global__ void ffn1_kernel(const float* __restrict__ x,
                            const float* __restrict__ W1) {
    int e = blockIdx.z;
    int cnt = g_cnt[e];
    int row0 = blockIdx.y * BM;
    if (row0 >= cnt) return;
    int fn0 = blockIdx.x * BN;
    int off = g_off[e];

    __shared__ float As[BK][BM + 4];
    __shared__ float Bs[BK][BN];

    int tid = threadIdx.x;
    int ar = tid >> 2, ac = (tid & 3) * 4;        // A load: 64 rows x 16 k
    int br = tid >> 4, bc = (tid & 15) * 4;       // B load: 16 k  x 64 f
    int ty = tid >> 4, tx = tid & 15;             // compute: 16x16 threads, 4x4 each

    bool validA = (row0 + ar) < cnt;
    int pA = validA ? g_pairlist[off + row0 + ar] : 0;
    int tokA = pA >> 1;
    const float* W1e = W1 + (size_t)e * D_MODEL * D_FF;

    float acc[4][4];
#pragma unroll
    for (int i = 0; i < 4; i++)
#pragma unroll
        for (int j = 0; j < 4; j++) acc[i][j] = 0.f;

    for (int k0 = 0; k0 < D_MODEL; k0 += BK) {
        float4 av = validA ? *(const float4*)&x[(size_t)tokA * D_MODEL + k0 + ac]
                           : make_float4(0.f, 0.f, 0.f, 0.f);
        As[ac + 0][ar] = av.x; As[ac + 1][ar] = av.y;
        As[ac + 2][ar] = av.z; As[ac + 3][ar] = av.w;
        *(float4*)&Bs[br][bc] =
            *(const float4*)&W1e[(size_t)(k0 + br) * D_FF + fn0 + bc];
        __syncthreads();
#pragma unroll
        for (int k = 0; k < BK; k++) {
            float4 a = *(float4*)&As[k][ty * 4];
            float4 b = *(float4*)&Bs[k][tx * 4];
            float ax[4] = {a.x, a.y, a.z, a.w};
            float bx[4] = {b.x, b.y, b.z, b.w};
#pragma unroll
            for (int i = 0; i < 4; i++)
#pragma unroll
                for (int j = 0; j < 4; j++) acc[i][j] += ax[i] * bx[j];
        }
        __syncthreads();
    }

#pragma unroll
    for (int i = 0; i < 4; i++) {
        int r = row0 + ty * 4 + i;
        if (r < cnt) {
            int p = g_pairlist[off + r];
            float4 o;
            o.x = gelu_exact(acc[i][0]); o.y = gelu_exact(acc[i][1]);
            o.z = gelu_exact(acc[i][2]); o.w = gelu_exact(acc[i][3]);
            *(float4*)&g_H[(size_t)p * D_FF + fn0 + tx * 4] = o;
        }
    }
}

// ------------- GEMM2: pairout[p,d] = w_p * ( H[p,:] @ W2[e] ) -------------
__global__ void ffn2_kernel(const float* __restrict__ W2) {
    int e = blockIdx.z;
    int cnt = g_cnt[e];
    int row0 = blockIdx.y * BM;
    if (row0 >= cnt) return;
    int fn0 = blockIdx.x * BN;  // over D_MODEL
    int off = g_off[e];

    __shared__ float As[BK][BM + 4];
    __shared__ float Bs[BK][BN];

    int tid = threadIdx.x;
    int ar = tid >> 2, ac = (tid & 3) * 4;
    int br = tid >> 4, bc = (tid & 15) * 4;
    int ty = tid >> 4, tx = tid & 15;

    bool validA = (row0 + ar) < cnt;
    int pA = validA ? g_pairlist[off + row0 + ar] : 0;
    const float* W2e = W2 + (size_t)e * D_FF * D_MODEL;

    float acc[4][4];
#pragma unroll
    for (int i = 0; i < 4; i++)
#pragma unroll
        for (int j = 0; j < 4; j++) acc[i][j] = 0.f;

    for (int k0 = 0; k0 < D_FF; k0 += BK) {
        float4 av = validA ? *(const float4*)&g_H[(size_t)pA * D_FF + k0 + ac]
                           : make_float4(0.f, 0.f, 0.f, 0.f);
        As[ac + 0][ar] = av.x; As[ac + 1][ar] = av.y;
        As[ac + 2][ar] = av.z; As[ac + 3][ar] = av.w;
        *(float4*)&Bs[br][bc] =
            *(const float4*)&W2e[(size_t)(k0 + br) * D_MODEL + fn0 + bc];
        __syncthreads();
#pragma unroll
        for (int k = 0; k < BK; k++) {
            float4 a = *(float4*)&As[k][ty * 4];
            float4 b = *(float4*)&Bs[k][tx * 4];
            float ax[4] = {a.x, a.y, a.z, a.w};
            float bx[4] = {b.x, b.y, b.z, b.w};
#pragma unroll
            for (int i = 0; i < 4; i++)
#pragma unroll
                for (int j = 0; j < 4; j++) acc[i][j] += ax[i] * bx[j];
        }
        __syncthreads();
    }

#pragma unroll
    for (int i = 0; i < 4; i++) {
        int r = row0 + ty * 4 + i;
        if (r < cnt) {
            int p = g_pairlist[off + r];
            float w = g_tokw[p];
            float4 o;
            o.x = w * acc[i][0]; o.y = w * acc[i][1];
            o.z = w * acc[i][2]; o.w = w * acc[i][3];
            *(float4*)&g_pairout[(size_t)p * D_MODEL + fn0 + tx * 4] = o;
        }
    }
}

// ---------------- combine: out[t] = pairout[2t] + pairout[2t+1] ----------------
__global__ void combine_kernel(float* __restrict__ out, int N) {
    int idx = blockIdx.x * blockDim.x + threadIdx.x;  // float4 index
    int total = N * (D_MODEL / 4);
    if (idx >= total) return;
    int t = idx / (D_MODEL / 4);
    int d4 = idx - t * (D_MODEL / 4);
    const float4* po = (const float4*)g_pairout;
    float4 a = po[(size_t)(2 * t) * (D_MODEL / 4) + d4];
    float4 b = po[(size_t)(2 * t + 1) * (D_MODEL / 4) + d4];
    float4 o = make_float4(a.x + b.x, a.y + b.y, a.z + b.z, a.w + b.w);
    ((float4*)out)[idx] = o;
}

extern "C" void kernel_launch(void* const* d_in, const int* in_sizes, int n_in,
                              void* d_out, int out_size) {
    const float* x  = (const float*)d_in[0];
    const float* gw = (const float*)d_in[1];
    const float* W1 = (const float*)d_in[2];
    const float* W2 = (const float*)d_in[3];
    int N = in_sizes[0] / D_MODEL;

    gate_kernel<<<(N + 7) / 8, 256>>>(x, gw, N);
    build_kernel<<<1, 256>>>(N);

    dim3 g1(D_FF / BN, (N + BM - 1) / BM, N_EXP);
    ffn1_kernel<<<g1, 256>>>(x, W1);

    dim3 g2(D_MODEL / BN, (N + BM - 1) / BM, N_EXP);
    ffn2_kernel<<<g2, 256>>>(W2);

    combine_kernel<<<(N * (D_MODEL / 4) + 255) / 256, 256>>>((float*)d_out, N);
}

// round 2
// speedup vs baseline: 1.0000x; 1.0000x over previous
#include <cuda_runtime.h>
#include <math.h>

#define D_MODEL 1024
#define D_FF    4096
#define N_EXP   8
#define MAX_N   4096
#define MAX_PAIRS (2*MAX_N)

// ---- scratch (static device globals; no runtime allocation) ----
__device__ float g_H[(size_t)MAX_PAIRS * D_FF];        // GELU(x@W1) per pair
__device__ float g_pairout[(size_t)MAX_PAIRS * D_MODEL]; // per-pair FFN output (weighted)
__device__ int   g_pairlist[MAX_PAIRS];                // pair ids sorted by expert (stable)
__device__ int   g_cnt[N_EXP];
__device__ int   g_off[N_EXP];
__device__ int   g_tokexp[MAX_PAIRS];                  // expert id per pair (pair = 2*t+slot)
__device__ float g_tokw[MAX_PAIRS];                    // gate weight per pair

__device__ __forceinline__ float gelu_exact(float v) {
    return 0.5f * v * (1.0f + erff(v * 0.70710678118654752440f));
}

// ---------------- gate: logits -> softmax -> top2 ----------------
__global__ void gate_kernel(const float* __restrict__ x,
                            const float* __restrict__ gw, int N) {
    __shared__ float s_gw[N_EXP][D_MODEL];
    int tid = threadIdx.x;
    for (int i = tid; i < N_EXP * D_MODEL; i += blockDim.x)
        s_gw[i >> 10][i & 1023] = gw[i];
    __syncthreads();

    int warp = tid >> 5, lane = tid & 31;
    int t = blockIdx.x * 8 + warp;
    if (t >= N) return;

    const float* xr = x + (size_t)t * D_MODEL;
    float acc[N_EXP];
#pragma unroll
    for (int e = 0; e < N_EXP; e++) acc[e] = 0.f;

    for (int d = lane; d < D_MODEL; d += 32) {
        float xv = xr[d];
#pragma unroll
        for (int e = 0; e < N_EXP; e++) acc[e] += xv * s_gw[e][d];
    }
#pragma unroll
    for (int e = 0; e < N_EXP; e++) {
#pragma unroll
        for (int o = 16; o > 0; o >>= 1)
            acc[e] += __shfl_xor_sync(0xffffffffu, acc[e], o);
    }

    if (lane == 0) {
        float mx = acc[0];
#pragma unroll
        for (int e = 1; e < N_EXP; e++) mx = fmaxf(mx, acc[e]);
        float p[N_EXP]; float sum = 0.f;
#pragma unroll
        for (int e = 0; e < N_EXP; e++) { p[e] = expf(acc[e] - mx); sum += p[e]; }
        float inv = 1.0f / sum;
#pragma unroll
        for (int e = 0; e < N_EXP; e++) p[e] *= inv;

        int e0 = 0;
#pragma unroll
        for (int e = 1; e < N_EXP; e++) if (p[e] > p[e0]) e0 = e;
        int e1 = (e0 == 0) ? 1 : 0;
#pragma unroll
        for (int e = 0; e < N_EXP; e++) if (e != e0 && p[e] > p[e1]) e1 = e;

        g_tokexp[2 * t + 0] = e0; g_tokw[2 * t + 0] = p[e0];
        g_tokexp[2 * t + 1] = e1; g_tokw[2 * t + 1] = p[e1];
    }
}

// ------- deterministic per-expert compaction (stable counting sort) -------
__global__ void build_kernel(int N) {
    __shared__ int s_cnt[N_EXP];
    int tid = threadIdx.x, warp = tid >> 5, lane = tid & 31;
    int total = 2 * N;

    // count pass: warp e counts entries with expert == e
    if (warp < N_EXP) {
        int c = 0;
        for (int i = lane; i < total; i += 32) c += (g_tokexp[i] == warp);
#pragma unroll
        for (int o = 16; o > 0; o >>= 1) c += __shfl_xor_sync(0xffffffffu, c, o);
        if (lane == 0) s_cnt[warp] = c;
    }
    __syncthreads();
    if (tid == 0) {
        int o = 0;
        for (int e = 0; e < N_EXP; e++) { g_off[e] = o; g_cnt[e] = s_cnt[e]; o += s_cnt[e]; }
    }
    __syncthreads();

    // place pass: stable order by pair id
    if (warp < N_EXP) {
        int run = g_off[warp];
        for (int base = 0; base < total; base += 32) {
            int i = base + lane;
            bool m = (i < total) && (g_tokexp[i] == warp);
            unsigned b = __ballot_sync(0xffffffffu, m);
            if (m) g_pairlist[run + __popc(b & ((1u << lane) - 1u))] = i;
            run += __popc(b);
        }
    }
}

// ---------------- GEMM1: H[p,f] = gelu( x[tok(p),:] @ W1[e] ) ----------------
#define BM 64
#define BN 64
#define BK 16

__global__ void ffn1_kernel(const float* __restrict__ x,
                            const float* __restrict__ W1) {
    int e = blockIdx.z;
    int cnt = g_cnt[e];
    int row0 = blockIdx.y * BM;
    if (row0 >= cnt) return;
    int fn0 = blockIdx.x * BN;
    int off = g_off[e];

    __shared__ float As[BK][BM + 4];
    __shared__ float Bs[BK][BN];

    int tid = threadIdx.x;
    int ar = tid >> 2, ac = (tid & 3) * 4;        // A load: 64 rows x 16 k
    int br = tid >> 4, bc = (tid & 15) * 4;       // B load: 16 k  x 64 f
    int ty = tid >> 4, tx = tid & 15;             // compute: 16x16 threads, 4x4 each

    bool validA = (row0 + ar) < cnt;
    int pA = validA ? g_pairlist[off + row0 + ar] : 0;
    int tokA = pA >> 1;
    const float* W1e = W1 + (size_t)e * D_MODEL * D_FF;

    float acc[4][4];
#pragma unroll
    for (int i = 0; i < 4; i++)
#pragma unroll
        for (int j = 0; j < 4; j++) acc[i][j] = 0.f;

    for (int k0 = 0; k0 < D_MODEL; k0 += BK) {
        float4 av = validA ? *(const float4*)&x[(size_t)tokA * D_MODEL + k0 + ac]
                           : make_float4(0.f, 0.f, 0.f, 0.f);
        As[ac + 0][ar] = av.x; As[ac + 1][ar] = av.y;
        As[ac + 2][ar] = av.z; As[ac + 3][ar] = av.w;
        *(float4*)&Bs[br][bc] =
            *(const float4*)&W1e[(size_t)(k0 + br) * D_FF + fn0 + bc];
        __syncthreads();
#pragma unroll
        for (int k = 0; k < BK; k++) {
            float4 a = *(float4*)&As[k][ty * 4];
            float4 b = *(float4*)&Bs[k][tx * 4];
            float ax[4] = {a.x, a.y, a.z, a.w};
            float bx[4] = {b.x, b.y, b.z, b.w};
#pragma unroll
            for (int i = 0; i < 4; i++)
#pragma unroll
                for (int j = 0; j < 4; j++) acc[i][j] += ax[i] * bx[j];
        }
        __syncthreads();
    }

#pragma unroll
    for (int i = 0; i < 4; i++) {
        int r = row0 + ty * 4 + i;
        if (r < cnt) {
            int p = g_pairlist[off + r];
            float4 o;
            o.x = gelu_exact(acc[i][0]); o.y = gelu_exact(acc[i][1]);
            o.z = gelu_exact(acc[i][2]); o.w = gelu_exact(acc[i][3]);
            *(float4*)&g_H[(size_t)p * D_FF + fn0 + tx * 4] = o;
        }
    }
}

// ------------- GEMM2: pairout[p,d] = w_p * ( H[p,:] @ W2[e] ) -------------
__global__ void ffn2_kernel(const float* __restrict__ W2) {
    int e = blockIdx.z;
    int cnt = g_cnt[e];
    int row0 = blockIdx.y * BM;
    if (row0 >= cnt) return;
    int fn0 = blockIdx.x * BN;  // over D_MODEL
    int off = g_off[e];

    __shared__ float As[BK][BM + 4];
    __shared__ float Bs[BK][BN];

    int tid = threadIdx.x;
    int ar = tid >> 2, ac = (tid & 3) * 4;
    int br = tid >> 4, bc = (tid & 15) * 4;
    int ty = tid >> 4, tx = tid & 15;

    bool validA = (row0 + ar) < cnt;
    int pA = validA ? g_pairlist[off + row0 + ar] : 0;
    const float* W2e = W2 + (size_t)e * D_FF * D_MODEL;

    float acc[4][4];
#pragma unroll
    for (int i = 0; i < 4; i++)
#pragma unroll
        for (int j = 0; j < 4; j++) acc[i][j] = 0.f;

    for (int k0 = 0; k0 < D_FF; k0 += BK) {
        float4 av = validA ? *(const float4*)&g_H[(size_t)pA * D_FF + k0 + ac]
                           : make_float4(0.f, 0.f, 0.f, 0.f);
        As[ac + 0][ar] = av.x; As[ac + 1][ar] = av.y;
        As[ac + 2][ar] = av.z; As[ac + 3][ar] = av.w;
        *(float4*)&Bs[br][bc] =
            *(const float4*)&W2e[(size_t)(k0 + br) * D_MODEL + fn0 + bc];
        __syncthreads();
#pragma unroll
        for (int k = 0; k < BK; k++) {
            float4 a = *(float4*)&As[k][ty * 4];
            float4 b = *(float4*)&Bs[k][tx * 4];
            float ax[4] = {a.x, a.y, a.z, a.w};
            float bx[4] = {b.x, b.y, b.z, b.w};
#pragma unroll
            for (int i = 0; i < 4; i++)
#pragma unroll
                for (int j = 0; j < 4; j++) acc[i][j] += ax[i] * bx[j];
        }
        __syncthreads();
    }

#pragma unroll
    for (int i = 0; i < 4; i++) {
        int r = row0 + ty * 4 + i;
        if (r < cnt) {
            int p = g_pairlist[off + r];
            float w = g_tokw[p];
            float4 o;
            o.x = w * acc[i][0]; o.y = w * acc[i][1];
            o.z = w * acc[i][2]; o.w = w * acc[i][3];
            *(float4*)&g_pairout[(size_t)p * D_MODEL + fn0 + tx * 4] = o;
        }
    }
}

// ---------------- combine: out[t] = pairout[2t] + pairout[2t+1] ----------------
__global__ void combine_kernel(float* __restrict__ out, int N) {
    int idx = blockIdx.x * blockDim.x + threadIdx.x;  // float4 index
    int total = N * (D_MODEL / 4);
    if (idx >= total) return;
    int t = idx / (D_MODEL / 4);
    int d4 = idx - t * (D_MODEL / 4);
    const float4* po = (const float4*)g_pairout;
    float4 a = po[(size_t)(2 * t) * (D_MODEL / 4) + d4];
    float4 b = po[(size_t)(2 * t + 1) * (D_MODEL / 4) + d4];
    float4 o = make_float4(a.x + b.x, a.y + b.y, a.z + b.z, a.w + b.w);
    ((float4*)out)[idx] = o;
}

extern "C" void kernel_launch(void* const* d_in, const int* in_sizes, int n_in,
                              void* d_out, int out_size) {
    const float* x  = (const float*)d_in[0];
    const float* gw = (const float*)d_in[1];
    const float* W1 = (const float*)d_in[2];
    const float* W2 = (const float*)d_in[3];
    int N = in_sizes[0] / D_MODEL;

    gate_kernel<<<(N + 7) / 8, 256>>>(x, gw, N);
    build_kernel<<<1, 256>>>(N);

    dim3 g1(D_FF / BN, (N + BM - 1) / BM, N_EXP);
    ffn1_kernel<<<g1, 256>>>(x, W1);

    dim3 g2(D_MODEL / BN, (N + BM - 1) / BM, N_EXP);
    ffn2_kernel<<<g2, 256>>>(W2);

    combine_kernel<<<(N * (D_MODEL / 4) + 255) / 256, 256>>>((float*)d_out, N);
}

// round 4
// speedup vs baseline: 2.2935x; 2.2935x over previous
#include <cuda_runtime.h>
#include <math.h>
#include <stdint.h>

#define D_MODEL 1024
#define D_FF    4096
#define N_EXP   8
#define MAX_N   4096
#define MAX_PAIRS (2*MAX_N)

// ---- scratch (static device globals; no runtime allocation) ----
__device__ float g_H[(size_t)MAX_PAIRS * D_FF];          // gelu(x@W1) per pair (fp32)
__device__ float g_pairout[(size_t)MAX_PAIRS * D_MODEL]; // per-pair weighted FFN output
__device__ int   g_pairlist[MAX_PAIRS];
__device__ int   g_cnt[N_EXP];
__device__ int   g_off[N_EXP];
__device__ int   g_tokexp[MAX_PAIRS];
__device__ float g_tokw[MAX_PAIRS];

__device__ __forceinline__ float gelu_exact(float v) {
    return 0.5f * v * (1.0f + erff(v * 0.70710678118654752440f));
}
__device__ __forceinline__ uint32_t f2tf32(float f) {
    uint32_t r; asm("cvt.rna.tf32.f32 %0, %1;" : "=r"(r) : "f"(f)); return r;
}
__device__ __forceinline__ void mma_tf32(float* d, const uint32_t* a, const uint32_t* b) {
    asm volatile(
        "mma.sync.aligned.m16n8k8.row.col.f32.tf32.tf32.f32 "
        "{%0,%1,%2,%3}, {%4,%5,%6,%7}, {%8,%9}, {%0,%1,%2,%3};"
        : "+f"(d[0]), "+f"(d[1]), "+f"(d[2]), "+f"(d[3])
        : "r"(a[0]), "r"(a[1]), "r"(a[2]), "r"(a[3]), "r"(b[0]), "r"(b[1]));
}

// ---------------- gate: logits -> softmax -> top2 ----------------
__global__ void gate_kernel(const float* __restrict__ x,
                            const float* __restrict__ gw, int N) {
    __shared__ float s_gw[N_EXP][D_MODEL];
    int tid = threadIdx.x;
    for (int i = tid; i < N_EXP * D_MODEL; i += blockDim.x)
        s_gw[i >> 10][i & 1023] = gw[i];
    __syncthreads();

    int warp = tid >> 5, lane = tid & 31;
    int t = blockIdx.x * 8 + warp;
    if (t >= N) return;

    const float* xr = x + (size_t)t * D_MODEL;
    float acc[N_EXP];
#pragma unroll
    for (int e = 0; e < N_EXP; e++) acc[e] = 0.f;
    for (int d = lane; d < D_MODEL; d += 32) {
        float xv = xr[d];
#pragma unroll
        for (int e = 0; e < N_EXP; e++) acc[e] += xv * s_gw[e][d];
    }
#pragma unroll
    for (int e = 0; e < N_EXP; e++) {
#pragma unroll
        for (int o = 16; o > 0; o >>= 1)
            acc[e] += __shfl_xor_sync(0xffffffffu, acc[e], o);
    }
    if (lane == 0) {
        float mx = acc[0];
#pragma unroll
        for (int e = 1; e < N_EXP; e++) mx = fmaxf(mx, acc[e]);
        float p[N_EXP]; float sum = 0.f;
#pragma unroll
        for (int e = 0; e < N_EXP; e++) { p[e] = expf(acc[e] - mx); sum += p[e]; }
        float inv = 1.0f / sum;
#pragma unroll
        for (int e = 0; e < N_EXP; e++) p[e] *= inv;
        int e0 = 0;
#pragma unroll
        for (int e = 1; e < N_EXP; e++) if (p[e] > p[e0]) e0 = e;
        int e1 = (e0 == 0) ? 1 : 0;
#pragma unroll
        for (int e = 0; e < N_EXP; e++) if (e != e0 && p[e] > p[e1]) e1 = e;
        g_tokexp[2 * t + 0] = e0; g_tokw[2 * t + 0] = p[e0];
        g_tokexp[2 * t + 1] = e1; g_tokw[2 * t + 1] = p[e1];
    }
}

// ------- deterministic per-expert compaction (stable counting sort) -------
__global__ void build_kernel(int N) {
    __shared__ int s_cnt[N_EXP];
    int tid = threadIdx.x, warp = tid >> 5, lane = tid & 31;
    int total = 2 * N;
    if (warp < N_EXP) {
        int c = 0;
        for (int i = lane; i < total; i += 32) c += (g_tokexp[i] == warp);
#pragma unroll
        for (int o = 16; o > 0; o >>= 1) c += __shfl_xor_sync(0xffffffffu, c, o);
        if (lane == 0) s_cnt[warp] = c;
    }
    __syncthreads();
    if (tid == 0) {
        int o = 0;
        for (int e = 0; e < N_EXP; e++) { g_off[e] = o; g_cnt[e] = s_cnt[e]; o += s_cnt[e]; }
    }
    __syncthreads();
    if (warp < N_EXP) {
        int run = g_off[warp];
        for (int base = 0; base < total; base += 32) {
            int i = base + lane;
            bool m = (i < total) && (g_tokexp[i] == warp);
            unsigned b = __ballot_sync(0xffffffffu, m);
            if (m) g_pairlist[run + __popc(b & ((1u << lane) - 1u))] = i;
            run += __popc(b);
        }
    }
}

// =================== mma.sync tf32 GEMM (fragment-layout SMEM) ===================
// MODE 0: H[p,n] = gelu( x[tok(p),:1024] @ W1[e][:,fn0+n] )
// MODE 1: pairout[p,n] = w_p * ( H[p,:4096] @ W2[e][:,fn0+n] )
//
// SMEM: [0:1024)  s_ptr[128]   input row pointers (gathered)
//       [1024:2048) s_optr[128] output row pointers
//       [2048:2560) s_w[128]    gate weights
//       [4096 + buf*32768): A frags 16KB, B frags 16KB
// A frag region: fa = mtile*4 + kstep (mtile 0..7, kstep 0..3), float4 per lane:
//   offset fa*512 + lane*16;  lane holds {a0,a1,a2,a3} of m16n8k8 tf32 A frag.
// B frag region: fb = ntile*4 + kstep (ntile 0..15), float2 per lane:
//   offset fb*256 + lane*8;   lane holds {b0,b1}.
#define SMEM_BUF0 4096
#define SMEM_BUFSTRIDE 32768
#define SMEM_TOT (4096 + 2*32768)

template <int MODE>
__global__ void __launch_bounds__(256, 2) moe_gemm(const float* __restrict__ Xin,
                                                   const float* __restrict__ W) {
    constexpr int Ktot = (MODE == 0) ? D_MODEL : D_FF;
    constexpr int ldW  = (MODE == 0) ? D_FF : D_MODEL;
    constexpr int ITERS = Ktot / 32;

    int e = blockIdx.z;
    int cnt = g_cnt[e];
    int row0 = blockIdx.y * 128;
    if (row0 >= cnt) return;
    int off = g_off[e];
    int fn0 = blockIdx.x * 128;
    const float* We = W + (size_t)e * Ktot * ldW;

    extern __shared__ __align__(128) char smem[];
    const float** s_ptr = (const float**)smem;
    float** s_optr = (float**)(smem + 1024);
    float*  s_w    = (float*)(smem + 2048);

    int tid = threadIdx.x, wid = tid >> 5, lane = tid & 31;

    if (tid < 128) {
        int r = row0 + tid;
        const float* ip = nullptr; float* op = nullptr; float wt = 0.f;
        if (r < cnt) {
            int p = g_pairlist[off + r];
            ip = (MODE == 0) ? (Xin + (size_t)(p >> 1) * D_MODEL)
                             : (g_H + (size_t)p * D_FF);
            op = (MODE == 0) ? (g_H + (size_t)p * D_FF + fn0)
                             : (g_pairout + (size_t)p * D_MODEL + fn0);
            wt = g_tokw[p];
        }
        s_ptr[tid] = ip; s_optr[tid] = op; s_w[tid] = wt;
    }
    __syncthreads();

    int g = lane >> 2, t = lane & 3;
    // A gather pointers for this lane (warp `wid` stages mtile == wid)
    const float* pLo = s_ptr[wid * 16 + g];
    const float* pHi = s_ptr[wid * 16 + 8 + g];
    // B column pointers (warp stages ntiles 2*wid, 2*wid+1)
    const float* q0 = We + fn0 + wid * 16 + g;
    const float* q1 = q0 + 8;

    char* Abuf[2] = { smem + SMEM_BUF0, smem + SMEM_BUF0 + SMEM_BUFSTRIDE };

    auto stage = [&](int it, int buf) {
        int k0 = it * 32;
        char* A = Abuf[buf];
        char* B = A + 16384;
#pragma unroll
        for (int q = 0; q < 4; q++) {      // A frags fa = wid*4+q (mtile=wid, kstep=q)
            int k = k0 + q * 8 + t;
            uint4 v;
            v.x = f2tf32(pLo ? pLo[k]     : 0.f);
            v.y = f2tf32(pHi ? pHi[k]     : 0.f);
            v.z = f2tf32(pLo ? pLo[k + 4] : 0.f);
            v.w = f2tf32(pHi ? pHi[k + 4] : 0.f);
            *(uint4*)(A + (wid * 4 + q) * 512 + lane * 16) = v;
        }
#pragma unroll
        for (int j = 0; j < 8; j++) {      // B frags fb = wid*8+j
            const float* qq = (j < 4) ? q0 : q1;
            int k = k0 + (j & 3) * 8 + t;
            uint2 v;
            v.x = f2tf32(qq[(size_t)k * ldW]);
            v.y = f2tf32(qq[(size_t)(k + 4) * ldW]);
            *(uint2*)(B + (wid * 8 + j) * 256 + lane * 8) = v;
        }
    };

    float d[4][4][4];
#pragma unroll
    for (int i = 0; i < 4; i++)
#pragma unroll
        for (int j = 0; j < 4; j++)
#pragma unroll
            for (int r = 0; r < 4; r++) d[i][j][r] = 0.f;

    int wm = wid >> 2, wn = wid & 3;   // warp computes rows wm*64.., cols wn*32..

    stage(0, 0);
    __syncthreads();

    for (int it = 0; it < ITERS; ++it) {
        if (it + 1 < ITERS) stage(it + 1, (it + 1) & 1);
        char* A = Abuf[it & 1];
        char* B = A + 16384;
#pragma unroll
        for (int ks = 0; ks < 4; ks++) {
            uint4 a[4]; uint2 b[4];
#pragma unroll
            for (int i = 0; i < 4; i++)
                a[i] = *(uint4*)(A + ((wm * 4 + i) * 4 + ks) * 512 + lane * 16);
#pragma unroll
            for (int j = 0; j < 4; j++)
                b[j] = *(uint2*)(B + ((wn * 4 + j) * 4 + ks) * 256 + lane * 8);
#pragma unroll
            for (int i = 0; i < 4; i++)
#pragma unroll
                for (int j = 0; j < 4; j++)
                    mma_tf32(d[i][j], (const uint32_t*)&a[i], (const uint32_t*)&b[j]);
        }
        __syncthreads();
    }

    // ---- epilogue straight from accumulators ----
#pragma unroll
    for (int i = 0; i < 4; i++) {
        int rl = wm * 64 + i * 16 + g;
        float* oL = s_optr[rl];
        float* oH = s_optr[rl + 8];
        float wL = s_w[rl], wH = s_w[rl + 8];
#pragma unroll
        for (int j = 0; j < 4; j++) {
            int c = wn * 32 + j * 8 + t * 2;
            if (oL) {
                float2 v;
                if (MODE == 0) { v.x = gelu_exact(d[i][j][0]); v.y = gelu_exact(d[i][j][1]); }
                else           { v.x = wL * d[i][j][0];        v.y = wL * d[i][j][1]; }
                *(float2*)(oL + c) = v;
            }
            if (oH) {
                float2 v;
                if (MODE == 0) { v.x = gelu_exact(d[i][j][2]); v.y = gelu_exact(d[i][j][3]); }
                else           { v.x = wH * d[i][j][2];        v.y = wH * d[i][j][3]; }
                *(float2*)(oH + c) = v;
            }
        }
    }
}

// ---------------- combine: out[t] = pairout[2t] + pairout[2t+1] ----------------
__global__ void combine_kernel(float* __restrict__ out, int N) {
    int idx = blockIdx.x * blockDim.x + threadIdx.x;
    int total = N * (D_MODEL / 4);
    if (idx >= total) return;
    int t = idx / (D_MODEL / 4);
    int d4 = idx - t * (D_MODEL / 4);
    const float4* po = (const float4*)g_pairout;
    float4 a = po[(size_t)(2 * t) * (D_MODEL / 4) + d4];
    float4 b = po[(size_t)(2 * t + 1) * (D_MODEL / 4) + d4];
    ((float4*)out)[idx] = make_float4(a.x + b.x, a.y + b.y, a.z + b.z, a.w + b.w);
}

extern "C" void kernel_launch(void* const* d_in, const int* in_sizes, int n_in,
                              void* d_out, int out_size) {
    const float* x  = (const float*)d_in[0];
    const float* gw = (const float*)d_in[1];
    const float* W1 = (const float*)d_in[2];
    const float* W2 = (const float*)d_in[3];
    int N = in_sizes[0] / D_MODEL;

    static bool attr_done = false;
    if (!attr_done) {
        cudaFuncSetAttribute(moe_gemm<0>, cudaFuncAttributeMaxDynamicSharedMemorySize, SMEM_TOT);
        cudaFuncSetAttribute(moe_gemm<1>, cudaFuncAttributeMaxDynamicSharedMemorySize, SMEM_TOT);
        attr_done = true;
    }

    gate_kernel<<<(N + 7) / 8, 256>>>(x, gw, N);
    build_kernel<<<1, 256>>>(N);

    // grid.y = 64 covers the worst-case single-expert skew (8192 pairs / 128)
    dim3 g1(D_FF / 128, 64, N_EXP);
    moe_gemm<0><<<g1, 256, SMEM_TOT>>>(x, W1);

    dim3 g2(D_MODEL / 128, 64, N_EXP);
    moe_gemm<1><<<g2, 256, SMEM_TOT>>>(nullptr, W2);

    combine_kernel<<<(N * (D_MODEL / 4) + 255) / 256, 256>>>((float*)d_out, N);
}

// round 5
// speedup vs baseline: 4.4297x; 1.9314x over previous
#include <cuda_runtime.h>
#include <cuda_fp16.h>
#include <math.h>
#include <stdint.h>

#define D_MODEL 1024
#define D_FF    4096
#define N_EXP   8
#define MAX_N   4096
#define MAX_PAIRS (2*MAX_N)

// ---- scratch (static device globals; no runtime allocation) ----
__device__ __half g_xh[(size_t)MAX_N * D_MODEL];           // x in half
__device__ __half g_W1t[(size_t)N_EXP * D_FF * D_MODEL];   // W1^T: [e][n=4096][k=1024] half
__device__ __half g_W2t[(size_t)N_EXP * D_MODEL * D_FF];   // W2^T: [e][n=1024][k=4096] half
__device__ __half g_Hh[(size_t)MAX_PAIRS * D_FF];          // gelu(x@W1) per pair, half
__device__ float  g_pairout[(size_t)MAX_PAIRS * D_MODEL];  // per-pair weighted FFN out
__device__ int    g_pairlist[MAX_PAIRS];
__device__ int    g_cnt[N_EXP];
__device__ int    g_off[N_EXP];
__device__ int    g_tokexp[MAX_PAIRS];
__device__ float  g_tokw[MAX_PAIRS];

__device__ __forceinline__ float gelu_exact(float v) {
    return 0.5f * v * (1.0f + erff(v * 0.70710678118654752440f));
}
__device__ __forceinline__ uint32_t smem_u32(const void* p) {
    uint32_t a;
    asm("{ .reg .u64 t; cvta.to.shared.u64 t, %1; cvt.u32.u64 %0, t; }" : "=r"(a) : "l"(p));
    return a;
}
__device__ __forceinline__ void cp_async16(uint32_t dst, const void* src, int srcsize) {
    asm volatile("cp.async.ca.shared.global [%0], [%1], 16, %2;"
                 :: "r"(dst), "l"(src), "r"(srcsize) : "memory");
}
__device__ __forceinline__ void cp_commit() { asm volatile("cp.async.commit_group;" ::: "memory"); }
__device__ __forceinline__ void cp_wait1()  { asm volatile("cp.async.wait_group 1;" ::: "memory"); }

__device__ __forceinline__ void ldsm_x4(uint32_t* r, uint32_t addr) {
    asm volatile("ldmatrix.sync.aligned.m8n8.x4.shared.b16 {%0,%1,%2,%3}, [%4];"
                 : "=r"(r[0]), "=r"(r[1]), "=r"(r[2]), "=r"(r[3]) : "r"(addr));
}
__device__ __forceinline__ void ldsm_x2(uint32_t* r, uint32_t addr) {
    asm volatile("ldmatrix.sync.aligned.m8n8.x2.shared.b16 {%0,%1}, [%2];"
                 : "=r"(r[0]), "=r"(r[1]) : "r"(addr));
}
__device__ __forceinline__ void mma_f16(float* d, const uint32_t* a, const uint32_t* b) {
    asm volatile(
        "mma.sync.aligned.m16n8k16.row.col.f32.f16.f16.f32 "
        "{%0,%1,%2,%3}, {%4,%5,%6,%7}, {%8,%9}, {%0,%1,%2,%3};"
        : "+f"(d[0]), "+f"(d[1]), "+f"(d[2]), "+f"(d[3])
        : "r"(a[0]), "r"(a[1]), "r"(a[2]), "r"(a[3]), "r"(b[0]), "r"(b[1]));
}

// ---------------- gate: logits -> softmax -> top2 ----------------
__global__ void gate_kernel(const float* __restrict__ x,
                            const float* __restrict__ gw, int N) {
    __shared__ float s_gw[N_EXP][D_MODEL];
    int tid = threadIdx.x;
    for (int i = tid; i < N_EXP * D_MODEL; i += blockDim.x)
        s_gw[i >> 10][i & 1023] = gw[i];
    __syncthreads();

    int warp = tid >> 5, lane = tid & 31;
    int t = blockIdx.x * 8 + warp;
    if (t >= N) return;

    const float* xr = x + (size_t)t * D_MODEL;
    float acc[N_EXP];
#pragma unroll
    for (int e = 0; e < N_EXP; e++) acc[e] = 0.f;
    for (int d = lane; d < D_MODEL; d += 32) {
        float xv = xr[d];
#pragma unroll
        for (int e = 0; e < N_EXP; e++) acc[e] += xv * s_gw[e][d];
    }
#pragma unroll
    for (int e = 0; e < N_EXP; e++) {
#pragma unroll
        for (int o = 16; o > 0; o >>= 1)
            acc[e] += __shfl_xor_sync(0xffffffffu, acc[e], o);
    }
    if (lane == 0) {
        float mx = acc[0];
#pragma unroll
        for (int e = 1; e < N_EXP; e++) mx = fmaxf(mx, acc[e]);
        float p[N_EXP]; float sum = 0.f;
#pragma unroll
        for (int e = 0; e < N_EXP; e++) { p[e] = expf(acc[e] - mx); sum += p[e]; }
        float inv = 1.0f / sum;
#pragma unroll
        for (int e = 0; e < N_EXP; e++) p[e] *= inv;
        int e0 = 0;
#pragma unroll
        for (int e = 1; e < N_EXP; e++) if (p[e] > p[e0]) e0 = e;
        int e1 = (e0 == 0) ? 1 : 0;
#pragma unroll
        for (int e = 0; e < N_EXP; e++) if (e != e0 && p[e] > p[e1]) e1 = e;
        g_tokexp[2 * t + 0] = e0; g_tokw[2 * t + 0] = p[e0];
        g_tokexp[2 * t + 1] = e1; g_tokw[2 * t + 1] = p[e1];
    }
}

// ------- deterministic per-expert compaction (stable counting sort) -------
__global__ void build_kernel(int N) {
    __shared__ int s_cnt[N_EXP];
    int tid = threadIdx.x, warp = tid >> 5, lane = tid & 31;
    int total = 2 * N;
    if (warp < N_EXP) {
        int c = 0;
        for (int i = lane; i < total; i += 32) c += (g_tokexp[i] == warp);
#pragma unroll
        for (int o = 16; o > 0; o >>= 1) c += __shfl_xor_sync(0xffffffffu, c, o);
        if (lane == 0) s_cnt[warp] = c;
    }
    __syncthreads();
    if (tid == 0) {
        int o = 0;
        for (int e = 0; e < N_EXP; e++) { g_off[e] = o; g_cnt[e] = s_cnt[e]; o += s_cnt[e]; }
    }
    __syncthreads();
    if (warp < N_EXP) {
        int run = g_off[warp];
        for (int base = 0; base < total; base += 32) {
            int i = base + lane;
            bool m = (i < total) && (g_tokexp[i] == warp);
            unsigned b = __ballot_sync(0xffffffffu, m);
            if (m) g_pairlist[run + __popc(b & ((1u << lane) - 1u))] = i;
            run += __popc(b);
        }
    }
}

// ---------------- prepass: convert & transpose ----------------
__global__ void convert_x_kernel(const float* __restrict__ x, int total4) {
    int i = blockIdx.x * blockDim.x + threadIdx.x;
    if (i >= total4) return;
    float4 v = ((const float4*)x)[i];
    __half2* o = (__half2*)g_xh;
    o[2 * i + 0] = __floats2half2_rn(v.x, v.y);
    o[2 * i + 1] = __floats2half2_rn(v.z, v.w);
}

// src [E][K][Nn] f32 -> dst [E][Nn][K] half  (tiled transpose)
__global__ void transpose_kernel(const float* __restrict__ src, __half* __restrict__ dst,
                                 int K, int Nn) {
    __shared__ float tile[32][33];
    int e = blockIdx.z;
    const float* s = src + (size_t)e * K * Nn;
    __half* d = dst + (size_t)e * K * Nn;
    int n0 = blockIdx.x * 32, k0 = blockIdx.y * 32;
    int tx = threadIdx.x, ty = threadIdx.y;  // 32 x 8
#pragma unroll
    for (int r = 0; r < 32; r += 8)
        tile[ty + r][tx] = s[(size_t)(k0 + ty + r) * Nn + n0 + tx];
    __syncthreads();
#pragma unroll
    for (int r = 0; r < 32; r += 8)
        d[(size_t)(n0 + ty + r) * K + k0 + tx] = __float2half_rn(tile[tx][ty + r]);
}

// =================== fp16 mma GEMM: cp.async + ldmatrix, 3-stage ===================
// 128x128 tile, BK=64. SMEM stage: A [128m][64k] half pitch 144B (18432B),
// B [128n][64k] half pitch 144B (18432B). 3 stages.
// smem: [0:1024)  s_aptr  (const __half* x128)
//       [1024:1536) s_pair (int x128)
//       [2048 + s*36864) stages
#define PITCH 144
#define A_STAGE_BYTES (128 * PITCH)
#define STAGE_BYTES   (2 * 128 * PITCH)
#define N_STAGES 3
#define SMEM_TOT (2048 + N_STAGES * STAGE_BYTES)

template <int MODE>
__global__ void __launch_bounds__(256, 2) moe_gemm(const __half* __restrict__ Wt) {
    constexpr int Ktot = (MODE == 0) ? D_MODEL : D_FF;
    constexpr int ITERS = Ktot / 64;

    int e = blockIdx.z;
    int cnt = g_cnt[e];
    int row0 = blockIdx.y * 128;
    if (row0 >= cnt) return;
    int off = g_off[e];
    int fn0 = blockIdx.x * 128;
    const __half* We = Wt + (size_t)e * Ktot * ((MODE == 0) ? D_FF : D_MODEL);

    extern __shared__ __align__(128) char smem[];
    const __half** s_aptr = (const __half**)smem;
    int* s_pair = (int*)(smem + 1024);
    uint32_t sb = smem_u32(smem);
    uint32_t stage_base = sb + 2048;

    int tid = threadIdx.x, wid = tid >> 5, lane = tid & 31;

    if (tid < 128) {
        int r = row0 + tid;
        const __half* ip = nullptr; int p = -1;
        if (r < cnt) {
            p = g_pairlist[off + r];
            ip = (MODE == 0) ? (g_xh + (size_t)(p >> 1) * D_MODEL)
                             : (g_Hh + (size_t)p * D_FF);
        }
        s_aptr[tid] = ip; s_pair[tid] = p;
    }
    __syncthreads();

    // staging assignment: thread -> row (tid>>1), half-row chunk group (tid&1)
    int srow = tid >> 1;
    int halfsel = tid & 1;                       // 0: k chunks 0..3, 1: 4..7
    const __half* arow = s_aptr[srow];
    int a_sz = arow ? 16 : 0;
    if (!arow) arow = g_xh;                      // safe dummy address
    const __half* brow = We + (size_t)(fn0 + srow) * Ktot;

    auto stage = [&](int it) {
        if (it < ITERS) {
            uint32_t sA = stage_base + (it % N_STAGES) * STAGE_BYTES + srow * PITCH + halfsel * 64;
            uint32_t sB = sA + A_STAGE_BYTES;
            const char* ga = (const char*)(arow + it * 64) + halfsel * 64;
            const char* gb = (const char*)(brow + it * 64) + halfsel * 64;
#pragma unroll
            for (int c = 0; c < 4; c++) cp_async16(sA + c * 16, ga + c * 16, a_sz);
#pragma unroll
            for (int c = 0; c < 4; c++) cp_async16(sB + c * 16, gb + c * 16, 16);
        }
        cp_commit();
    };

    float d[4][4][4];
#pragma unroll
    for (int i = 0; i < 4; i++)
#pragma unroll
        for (int j = 0; j < 4; j++)
#pragma unroll
            for (int r = 0; r < 4; r++) d[i][j][r] = 0.f;

    int wm = wid >> 2, wn = wid & 3;  // warp tile: rows wm*64.., cols wn*32..

    // ldmatrix lane address components
    int a_row_l = (lane & 15);        // row within 16-row mtile
    int a_koff  = (lane >> 4) * 16;   // +16B for k+8 halves
    int b_row_l = (lane & 7);
    int b_koff  = ((lane >> 3) & 1) * 16;

    stage(0);
    stage(1);

    for (int it = 0; it < ITERS; ++it) {
        cp_wait1();
        __syncthreads();
        uint32_t A = stage_base + (it % N_STAGES) * STAGE_BYTES;
        uint32_t B = A + A_STAGE_BYTES;
#pragma unroll
        for (int ks = 0; ks < 4; ks++) {
            uint32_t a[4][4], b[4][2];
#pragma unroll
            for (int i = 0; i < 4; i++)
                ldsm_x4(a[i], A + (wm * 64 + i * 16 + a_row_l) * PITCH + ks * 32 + a_koff);
#pragma unroll
            for (int j = 0; j < 4; j++)
                ldsm_x2(b[j], B + (wn * 32 + j * 8 + b_row_l) * PITCH + ks * 32 + b_koff);
#pragma unroll
            for (int i = 0; i < 4; i++)
#pragma unroll
                for (int j = 0; j < 4; j++)
                    mma_f16(d[i][j], a[i], b[j]);
        }
        __syncthreads();
        stage(it + 2);
    }

    // ---- epilogue from accumulators ----
    int g = lane >> 2, t4 = lane & 3;
#pragma unroll
    for (int i = 0; i < 4; i++) {
        int rl = wm * 64 + i * 16 + g;
        int pL = s_pair[rl], pH = s_pair[rl + 8];
#pragma unroll
        for (int j = 0; j < 4; j++) {
            int c = wn * 32 + j * 8 + t4 * 2;
            if (MODE == 0) {
                if (pL >= 0) {
                    __half2* o = (__half2*)(g_Hh + (size_t)pL * D_FF + fn0 + c);
                    *o = __floats2half2_rn(gelu_exact(d[i][j][0]), gelu_exact(d[i][j][1]));
                }
                if (pH >= 0) {
                    __half2* o = (__half2*)(g_Hh + (size_t)pH * D_FF + fn0 + c);
                    *o = __floats2half2_rn(gelu_exact(d[i][j][2]), gelu_exact(d[i][j][3]));
                }
            } else {
                if (pL >= 0) {
                    float w = g_tokw[pL];
                    *(float2*)(g_pairout + (size_t)pL * D_MODEL + fn0 + c) =
                        make_float2(w * d[i][j][0], w * d[i][j][1]);
                }
                if (pH >= 0) {
                    float w = g_tokw[pH];
                    *(float2*)(g_pairout + (size_t)pH * D_MODEL + fn0 + c) =
                        make_float2(w * d[i][j][2], w * d[i][j][3]);
                }
            }
        }
    }
}

// ---------------- combine: out[t] = pairout[2t] + pairout[2t+1] ----------------
__global__ void combine_kernel(float* __restrict__ out, int N) {
    int idx = blockIdx.x * blockDim.x + threadIdx.x;
    int total = N * (D_MODEL / 4);
    if (idx >= total) return;
    int t = idx / (D_MODEL / 4);
    int d4 = idx - t * (D_MODEL / 4);
    const float4* po = (const float4*)g_pairout;
    float4 a = po[(size_t)(2 * t) * (D_MODEL / 4) + d4];
    float4 b = po[(size_t)(2 * t + 1) * (D_MODEL / 4) + d4];
    ((float4*)out)[idx] = make_float4(a.x + b.x, a.y + b.y, a.z + b.z, a.w + b.w);
}

extern "C" void kernel_launch(void* const* d_in, const int* in_sizes, int n_in,
                              void* d_out, int out_size) {
    const float* x  = (const float*)d_in[0];
    const float* gw = (const float*)d_in[1];
    const float* W1 = (const float*)d_in[2];
    const float* W2 = (const float*)d_in[3];
    int N = in_sizes[0] / D_MODEL;

    static bool attr_done = false;
    if (!attr_done) {
        cudaFuncSetAttribute(moe_gemm<0>, cudaFuncAttributeMaxDynamicSharedMemorySize, SMEM_TOT);
        cudaFuncSetAttribute(moe_gemm<1>, cudaFuncAttributeMaxDynamicSharedMemorySize, SMEM_TOT);
        attr_done = true;
    }

    gate_kernel<<<(N + 7) / 8, 256>>>(x, gw, N);
    build_kernel<<<1, 256>>>(N);

    // prepass conversions
    convert_x_kernel<<<(N * D_MODEL / 4 + 255) / 256, 256>>>(x, N * D_MODEL / 4);
    {
        __half* w1t; cudaGetSymbolAddress((void**)&w1t, g_W1t);
        __half* w2t; cudaGetSymbolAddress((void**)&w2t, g_W2t);
        dim3 blk(32, 8);
        dim3 gt1(D_FF / 32, D_MODEL / 32, N_EXP);
        transpose_kernel<<<gt1, blk>>>(W1, w1t, D_MODEL, D_FF);
        dim3 gt2(D_MODEL / 32, D_FF / 32, N_EXP);
        transpose_kernel<<<gt2, blk>>>(W2, w2t, D_FF, D_MODEL);
    }

    __half* w1t; cudaGetSymbolAddress((void**)&w1t, g_W1t);
    __half* w2t; cudaGetSymbolAddress((void**)&w2t, g_W2t);

    dim3 g1(D_FF / 128, 64, N_EXP);
    moe_gemm<0><<<g1, 256, SMEM_TOT>>>(w1t);

    dim3 g2(D_MODEL / 128, 64, N_EXP);
    moe_gemm<1><<<g2, 256, SMEM_TOT>>>(w2t);

    combine_kernel<<<(N * (D_MODEL / 4) + 255) / 256, 256>>>((float*)d_out, N);
}